// round 5
// baseline (speedup 1.0000x reference)
#include <cuda_runtime.h>
#include <cstdint>
#include <cstddef>
#include <math_constants.h>

// ---------------- problem constants ----------------
constexpr int B_   = 4;
constexpr int S_   = 2048;
constexpr int HD_  = 1024;
constexpr int NH_  = 8;
constexpr int DK_  = 128;
constexpr int WA_  = 67;
constexpr int BH_  = B_ * NH_;         // 32
constexpr int OUT1W_ = NH_ * WA_;      // 536

// qkv geometry
constexpr int KC   = 16;               // k-chunk
constexpr int LQK  = 20;               // smem stride (conflict-free: gcd(20,32)=4 cycle)
constexpr int STG  = 2 * 128 * LQK;    // floats per stage (A+B)

// fused geometry
constexpr int KT   = 32;               // seq cols per k-tile
constexpr int QLD  = 132;
constexpr int KLD  = 132;
constexpr int CLD  = 36;
constexpr int NP   = 72;               // padded wavelet rows

// ---------------- device scratch ----------------
__device__ float g_q  [(size_t)BH_ * S_ * DK_];
__device__ float g_k  [(size_t)BH_ * S_ * DK_];
__device__ float g_v  [(size_t)BH_ * S_ * DK_];
__device__ float g_cDT[(size_t)BH_ * WA_ * S_];   // transposed cD: [bh][wa][s]

__constant__ float REV_LO[8] = {
    0.23037781330885523f,  0.7148465705525415f,  0.6308807679295904f,
   -0.02798376941698385f, -0.18703481171888114f, 0.030841381835986965f,
    0.032883011666982945f,-0.010597401784997278f };
__constant__ float REV_HI[8] = {
   -0.010597401784997278f,-0.032883011666982945f, 0.030841381835986965f,
    0.18703481171888114f, -0.02798376941698385f, -0.6308807679295904f,
    0.7148465705525415f,  -0.23037781330885523f };

// ---------------- helpers ----------------
static __device__ __forceinline__ float tf32r(float x) {
    uint32_t u; asm("cvt.rna.tf32.f32 %0, %1;" : "=r"(u) : "f"(x));
    return __uint_as_float(u);
}
static __device__ __forceinline__ float4 tf32r4(float4 v) {
    v.x = tf32r(v.x); v.y = tf32r(v.y); v.z = tf32r(v.z); v.w = tf32r(v.w);
    return v;
}
static __device__ __forceinline__ void mma8(float* c,
    float a0, float a1, float a2, float a3, float b0, float b1)
{
    asm volatile(
        "mma.sync.aligned.m16n8k8.row.col.f32.tf32.tf32.f32 "
        "{%0,%1,%2,%3},{%4,%5,%6,%7},{%8,%9},{%0,%1,%2,%3};"
        : "+f"(c[0]), "+f"(c[1]), "+f"(c[2]), "+f"(c[3])
        : "r"(__float_as_uint(a0)), "r"(__float_as_uint(a1)),
          "r"(__float_as_uint(a2)), "r"(__float_as_uint(a3)),
          "r"(__float_as_uint(b0)), "r"(__float_as_uint(b1)));
}

constexpr size_t SMEM_QKV   = (size_t)2 * STG * 4;                       // 40960
constexpr size_t SMEM_FUSED = (size_t)(128 * QLD + KT * KLD + NP * CLD) * 4; // 94848

// =====================================================================
// Kernel 1: QKV, y = x @ W^T.  block 128x128, warps 4x2, warp 32x64,
// 2-stage double-buffered smem, 1 barrier per 16-chunk.
// grid (HD/128, 8192/128, 3)
// =====================================================================
__global__ void __launch_bounds__(256, 2)
qkv_gemm(const float* __restrict__ x, const float* __restrict__ Wq,
         const float* __restrict__ Wk, const float* __restrict__ Wv)
{
    extern __shared__ float sm[];

    const int mode = blockIdx.z;
    const float* Wm = (mode == 0) ? Wq : (mode == 1) ? Wk : Wv;
    float* dst      = (mode == 0) ? g_q : (mode == 1) ? g_k : g_v;
    const float scale = (mode == 0) ? 0.08838834764831845f : 1.0f;

    const int tid = threadIdx.x;
    const int m0 = blockIdx.y * 128, n0 = blockIdx.x * 128;
    const int ldr = tid >> 1, ldc = (tid & 1) * 8;
    const float* ag = x  + (size_t)(m0 + ldr) * HD_ + ldc;
    const float* bg = Wm + (size_t)(n0 + ldr) * HD_ + ldc;

    const int lane = tid & 31, wid = tid >> 5;
    const int wm = wid >> 1, wn = wid & 1, grp = lane >> 2, q4 = lane & 3;
    const int abase = (wm * 32 + grp) * LQK + q4;
    const int bbase = (wn * 64 + grp) * LQK + q4;

    float acc[2][8][4] = {};
    float4 ra[2], rb[2];

    // prologue: chunk 0
#pragma unroll
    for (int i = 0; i < 2; ++i) { ra[i] = *(const float4*)(ag + i * 4);
                                  rb[i] = *(const float4*)(bg + i * 4); }
    {
        float* As = sm, * Bs = sm + 128 * LQK;
#pragma unroll
        for (int i = 0; i < 2; ++i) {
            *(float4*)&As[ldr * LQK + ldc + i * 4] = tf32r4(ra[i]);
            *(float4*)&Bs[ldr * LQK + ldc + i * 4] = tf32r4(rb[i]);
        }
    }
    __syncthreads();

    constexpr int NCH = HD_ / KC;   // 64
    for (int kc = 0; kc < NCH; ++kc) {
        const float* As = sm + (kc & 1) * STG;
        const float* Bs = As + 128 * LQK;

        if (kc + 1 < NCH) {
#pragma unroll
            for (int i = 0; i < 2; ++i) {
                ra[i] = *(const float4*)(ag + (kc + 1) * KC + i * 4);
                rb[i] = *(const float4*)(bg + (kc + 1) * KC + i * 4);
            }
        }

#pragma unroll
        for (int k8 = 0; k8 < KC; k8 += 8) {
            float a[2][4], b[8][2];
#pragma unroll
            for (int i = 0; i < 2; ++i) {
                const int o = abase + i * 16 * LQK + k8;
                a[i][0] = As[o];     a[i][1] = As[o + 8 * LQK];
                a[i][2] = As[o + 4]; a[i][3] = As[o + 8 * LQK + 4];
            }
#pragma unroll
            for (int j = 0; j < 8; ++j) {
                const int o = bbase + j * 8 * LQK + k8;
                b[j][0] = Bs[o]; b[j][1] = Bs[o + 4];
            }
#pragma unroll
            for (int i = 0; i < 2; ++i)
#pragma unroll
                for (int j = 0; j < 8; ++j)
                    mma8(acc[i][j], a[i][0], a[i][1], a[i][2], a[i][3], b[j][0], b[j][1]);
        }

        if (kc + 1 < NCH) {
            float* An = sm + ((kc + 1) & 1) * STG;
            float* Bn = An + 128 * LQK;
#pragma unroll
            for (int i = 0; i < 2; ++i) {
                *(float4*)&An[ldr * LQK + ldc + i * 4] = tf32r4(ra[i]);
                *(float4*)&Bn[ldr * LQK + ldc + i * 4] = tf32r4(rb[i]);
            }
            __syncthreads();
        }
    }

#pragma unroll
    for (int i = 0; i < 2; ++i) {
#pragma unroll
        for (int r = 0; r < 2; ++r) {
            const int m = m0 + wm * 32 + i * 16 + grp + r * 8;
            const int bb = m >> 11, s = m & (S_ - 1);
#pragma unroll
            for (int j = 0; j < 8; ++j) {
                const int n = n0 + wn * 64 + j * 8 + 2 * q4;
                const int h = n >> 7, d = n & 127;
                float2 w = make_float2(acc[i][j][2 * r] * scale, acc[i][j][2 * r + 1] * scale);
                *(float2*)&dst[((size_t)(bb * NH_ + h) * S_ + s) * DK_ + d] = w;
            }
        }
    }
}

// =====================================================================
// Kernel 2: db4 DWT of v. cA -> out2 (raw), cD -> g_cDT (transposed).
// =====================================================================
__global__ void dwt_kernel(float* __restrict__ out2)
{
    const int rowi = blockIdx.x;
    const float* vr = g_v + (size_t)rowi * DK_;
    __shared__ float e[141];
    const int t = threadIdx.x;

    e[t + 6] = vr[t];
    if (t < 6)  e[t]       = vr[5 - t];
    if (t < 7)  e[134 + t] = vr[127 - t];
    __syncthreads();

    if (t < WA_) {
        float a = 0.f, d = 0.f;
#pragma unroll
        for (int u = 0; u < 8; ++u) {
            const float xv = e[2 * t + u];
            a += xv * REV_LO[u];
            d += xv * REV_HI[u];
        }
        out2[(size_t)rowi * WA_ + t] = a;
        const int bh = rowi >> 11, s = rowi & (S_ - 1);
        g_cDT[((size_t)bh * WA_ + t) * S_ + s] = d;
    }
}

// =====================================================================
// Kernel 3: FUSED attention, occ-2 variant.  KT=32, K kept fp32 in smem
// (split at frag load), P kept in registers (shfl c-frag -> a-frag).
// grid (16, 32), 256 threads, 92.6KB smem -> 2 CTAs/SM.
// =====================================================================
__global__ void __launch_bounds__(256, 2)
fused_attn(float* __restrict__ out1)
{
    extern __shared__ float sm[];
    float* Qs  = sm;                              // 128 x QLD (fp32)
    float* Kf  = Qs + 128 * QLD;                  // KT x KLD (fp32)
    float* CDs = Kf + KT * KLD;                   // NP x CLD (tf32)

    const int bh = blockIdx.y;
    const int q0 = blockIdx.x * 128;
    const int tid = threadIdx.x, lane = tid & 31, wid = tid >> 5;
    const int grp = lane >> 2, q4 = lane & 3;

    // ---- Q tile load (128 x 128 fp32) ----
    {
        const int c = (tid & 31) * 4;
#pragma unroll
        for (int p = 0; p < 16; ++p) {
            const int r = (tid >> 5) + p * 8;
            *(float4*)&Qs[r * QLD + c] =
                *(const float4*)(g_q + ((size_t)bh * S_ + q0 + r) * DK_ + c);
        }
    }

    const int krow = tid >> 3;            // 0..31
    const int kcol = (tid & 7) * 16;      // dk base for K loads (4 float4)
    const int ccol = (tid & 7) * 4;       // seq-in-tile base for cD loads
    float4 kreg[4], creg[3];
#pragma unroll
    for (int i = 0; i < 4; ++i)
        kreg[i] = *(const float4*)(g_k + ((size_t)bh * S_ + krow) * DK_ + kcol + i * 4);
#pragma unroll
    for (int it = 0; it < 3; ++it) {
        const int n = krow + it * 32;
        creg[it] = (n < WA_) ? *(const float4*)(g_cDT + ((size_t)bh * WA_ + n) * S_ + ccol)
                             : make_float4(0.f, 0.f, 0.f, 0.f);
    }

    float oacc[9][4] = {};
    float m0v = -CUDART_INF_F, m1v = -CUDART_INF_F;
    float l0 = 0.f, l1 = 0.f;
    const int arow = wid * 16 + grp;
    const int srcA = (grp << 2) | (q4 >> 1);
    const int srcB = srcA + 2;
    const bool par = (q4 & 1) != 0;

    for (int kc = 0; kc < S_ / KT; ++kc) {
        __syncthreads();   // previous iteration's smem reads done
#pragma unroll
        for (int i = 0; i < 4; ++i)
            *(float4*)&Kf[krow * KLD + kcol + i * 4] = kreg[i];
#pragma unroll
        for (int it = 0; it < 3; ++it) {
            const int n = krow + it * 32;
            if (n < NP) *(float4*)&CDs[n * CLD + ccol] = tf32r4(creg[it]);
        }
        __syncthreads();
        if (kc + 1 < S_ / KT) {
            const size_t kr0 = (size_t)bh * S_ + (kc + 1) * KT + krow;
#pragma unroll
            for (int i = 0; i < 4; ++i)
                kreg[i] = *(const float4*)(g_k + kr0 * DK_ + kcol + i * 4);
#pragma unroll
            for (int it = 0; it < 3; ++it) {
                const int n = krow + it * 32;
                creg[it] = (n < WA_)
                    ? *(const float4*)(g_cDT + ((size_t)bh * WA_ + n) * S_ + (kc + 1) * KT + ccol)
                    : make_float4(0.f, 0.f, 0.f, 0.f);
            }
        }

        // ---- S-tile: 16 rows x 32 cols per warp, split-tf32 ----
        float sp[4][4] = {};
#pragma unroll
        for (int k8 = 0; k8 < DK_; k8 += 8) {
            const int o = arow * QLD + q4 + k8;
            const float f0 = Qs[o], f1 = Qs[o + 8 * QLD];
            const float f2 = Qs[o + 4], f3 = Qs[o + 8 * QLD + 4];
            const float ah0 = tf32r(f0), ah1 = tf32r(f1), ah2 = tf32r(f2), ah3 = tf32r(f3);
            const float al0 = tf32r(f0 - ah0), al1 = tf32r(f1 - ah1);
            const float al2 = tf32r(f2 - ah2), al3 = tf32r(f3 - ah3);
#pragma unroll
            for (int j = 0; j < 4; ++j) {
                const int ob = (8 * j + grp) * KLD + q4 + k8;
                const float g0 = Kf[ob], g1 = Kf[ob + 4];
                const float bh0 = tf32r(g0), bh1 = tf32r(g1);
                const float bl0 = tf32r(g0 - bh0), bl1 = tf32r(g1 - bh1);
                mma8(sp[j], ah0, ah1, ah2, ah3, bh0, bh1);
                mma8(sp[j], ah0, ah1, ah2, ah3, bl0, bl1);
                mma8(sp[j], al0, al1, al2, al3, bh0, bh1);
            }
        }

        // ---- online softmax (warp-local; rows grp and grp+8) ----
        float tm0 = sp[0][0], tm1 = sp[0][2];
#pragma unroll
        for (int j = 0; j < 4; ++j) {
            tm0 = fmaxf(tm0, fmaxf(sp[j][0], sp[j][1]));
            tm1 = fmaxf(tm1, fmaxf(sp[j][2], sp[j][3]));
        }
        tm0 = fmaxf(tm0, __shfl_xor_sync(0xFFFFFFFFu, tm0, 1));
        tm0 = fmaxf(tm0, __shfl_xor_sync(0xFFFFFFFFu, tm0, 2));
        tm1 = fmaxf(tm1, __shfl_xor_sync(0xFFFFFFFFu, tm1, 1));
        tm1 = fmaxf(tm1, __shfl_xor_sync(0xFFFFFFFFu, tm1, 2));
        const float mn0 = fmaxf(m0v, tm0), mn1 = fmaxf(m1v, tm1);
        const float a0s = __expf(m0v - mn0), a1s = __expf(m1v - mn1);

        float ts0 = 0.f, ts1 = 0.f;
#pragma unroll
        for (int j = 0; j < 4; ++j) {
            sp[j][0] = __expf(sp[j][0] - mn0);
            sp[j][1] = __expf(sp[j][1] - mn0);
            sp[j][2] = __expf(sp[j][2] - mn1);
            sp[j][3] = __expf(sp[j][3] - mn1);
            ts0 += sp[j][0] + sp[j][1];
            ts1 += sp[j][2] + sp[j][3];
        }
        ts0 += __shfl_xor_sync(0xFFFFFFFFu, ts0, 1);
        ts0 += __shfl_xor_sync(0xFFFFFFFFu, ts0, 2);
        ts1 += __shfl_xor_sync(0xFFFFFFFFu, ts1, 1);
        ts1 += __shfl_xor_sync(0xFFFFFFFFu, ts1, 2);
        l0 = l0 * a0s + ts0;
        l1 = l1 * a1s + ts1;
        m0v = mn0; m1v = mn1;
#pragma unroll
        for (int n = 0; n < 9; ++n) {
            oacc[n][0] *= a0s; oacc[n][1] *= a0s;
            oacc[n][2] *= a1s; oacc[n][3] *= a1s;
        }

        // ---- O += P @ cD^T; P a-frags built from c-frags via shfl ----
#pragma unroll
        for (int kt = 0; kt < 4; ++kt) {
            const float e0 = __shfl_sync(0xFFFFFFFFu, sp[kt][0], srcA);
            const float e1 = __shfl_sync(0xFFFFFFFFu, sp[kt][1], srcA);
            const float g0 = __shfl_sync(0xFFFFFFFFu, sp[kt][0], srcB);
            const float g1 = __shfl_sync(0xFFFFFFFFu, sp[kt][1], srcB);
            const float h0 = __shfl_sync(0xFFFFFFFFu, sp[kt][2], srcA);
            const float h1 = __shfl_sync(0xFFFFFFFFu, sp[kt][3], srcA);
            const float i0 = __shfl_sync(0xFFFFFFFFu, sp[kt][2], srcB);
            const float i1 = __shfl_sync(0xFFFFFFFFu, sp[kt][3], srcB);
            const float a0 = tf32r(par ? e1 : e0);
            const float a2 = tf32r(par ? g1 : g0);
            const float a1 = tf32r(par ? h1 : h0);
            const float a3 = tf32r(par ? i1 : i0);
#pragma unroll
            for (int n = 0; n < 9; ++n) {
                const int ob = (8 * n + grp) * CLD + q4 + kt * 8;
                mma8(oacc[n], a0, a1, a2, a3, CDs[ob], CDs[ob + 4]);
            }
        }
    }

    // ---- epilogue: normalize and store ----
    const int bb = bh >> 3, hh = bh & 7;
    const float i0 = 1.0f / l0, i1 = 1.0f / l1;
    const int s0 = q0 + wid * 16 + grp, s1 = s0 + 8;
    float* o0 = out1 + (size_t)(bb * S_ + s0) * OUT1W_ + hh * WA_;
    float* o1 = out1 + (size_t)(bb * S_ + s1) * OUT1W_ + hh * WA_;
#pragma unroll
    for (int n = 0; n < 9; ++n) {
        const int c = 8 * n + 2 * q4;
        if (c < WA_)     { o0[c]     = oacc[n][0] * i0; o1[c]     = oacc[n][2] * i1; }
        if (c + 1 < WA_) { o0[c + 1] = oacc[n][1] * i0; o1[c + 1] = oacc[n][3] * i1; }
    }
}

// =====================================================================
extern "C" void kernel_launch(void* const* d_in, const int* in_sizes, int n_in,
                              void* d_out, int out_size)
{
    const float* x  = (const float*)d_in[0];
    const float* Wq = (const float*)d_in[1];
    const float* Wk = (const float*)d_in[2];
    const float* Wv = (const float*)d_in[3];

    float* out1 = (float*)d_out;
    float* out2 = out1 + (size_t)out_size / 2;

    cudaFuncSetAttribute(qkv_gemm,   cudaFuncAttributeMaxDynamicSharedMemorySize, (int)SMEM_QKV);
    cudaFuncSetAttribute(fused_attn, cudaFuncAttributeMaxDynamicSharedMemorySize, (int)SMEM_FUSED);

    qkv_gemm  <<<dim3(HD_ / 128, (B_ * S_) / 128, 3), 256, SMEM_QKV>>>(x, Wq, Wk, Wv);
    dwt_kernel<<<BH_ * S_, 128>>>(out2);
    fused_attn<<<dim3(S_ / 128, BH_), 256, SMEM_FUSED>>>(out1);
}

// round 7
// speedup vs baseline: 1.1274x; 1.1274x over previous
#include <cuda_runtime.h>
#include <cstdint>
#include <cstddef>
#include <math_constants.h>

// ---------------- problem constants ----------------
constexpr int B_   = 4;
constexpr int S_   = 2048;
constexpr int HD_  = 1024;
constexpr int NH_  = 8;
constexpr int DK_  = 128;
constexpr int WA_  = 67;
constexpr int BH_  = B_ * NH_;         // 32
constexpr int OUT1W_ = NH_ * WA_;      // 536

// qkv geometry (cp.async multistage)
constexpr int LQK  = 20;               // smem stride (conflict-free frag loads)
constexpr int STGF = (128 + 64) * LQK; // floats per stage = 3840
constexpr int NSTG = 4;

// fused geometry (R4 settings)
constexpr int KT   = 64;
constexpr int QLD  = 132;
constexpr int CLD  = 68;
constexpr int NP   = 72;

// ---------------- device scratch ----------------
__device__ float g_q  [(size_t)BH_ * S_ * DK_];
__device__ float g_k  [(size_t)BH_ * S_ * DK_];
__device__ float g_v  [(size_t)BH_ * S_ * DK_];
__device__ float g_cDT[(size_t)BH_ * WA_ * S_];   // transposed cD: [bh][wa][s]

__constant__ float REV_LO[8] = {
    0.23037781330885523f,  0.7148465705525415f,  0.6308807679295904f,
   -0.02798376941698385f, -0.18703481171888114f, 0.030841381835986965f,
    0.032883011666982945f,-0.010597401784997278f };
__constant__ float REV_HI[8] = {
   -0.010597401784997278f,-0.032883011666982945f, 0.030841381835986965f,
    0.18703481171888114f, -0.02798376941698385f, -0.6308807679295904f,
    0.7148465705525415f,  -0.23037781330885523f };

// ---------------- helpers ----------------
static __device__ __forceinline__ float tf32r(float x) {
    uint32_t u; asm("cvt.rna.tf32.f32 %0, %1;" : "=r"(u) : "f"(x));
    return __uint_as_float(u);
}
static __device__ __forceinline__ float4 tf32r4(float4 v) {
    v.x = tf32r(v.x); v.y = tf32r(v.y); v.z = tf32r(v.z); v.w = tf32r(v.w);
    return v;
}
static __device__ __forceinline__ void mma8(float* c,
    float a0, float a1, float a2, float a3, float b0, float b1)
{
    asm volatile(
        "mma.sync.aligned.m16n8k8.row.col.f32.tf32.tf32.f32 "
        "{%0,%1,%2,%3},{%4,%5,%6,%7},{%8,%9},{%0,%1,%2,%3};"
        : "+f"(c[0]), "+f"(c[1]), "+f"(c[2]), "+f"(c[3])
        : "r"(__float_as_uint(a0)), "r"(__float_as_uint(a1)),
          "r"(__float_as_uint(a2)), "r"(__float_as_uint(a3)),
          "r"(__float_as_uint(b0)), "r"(__float_as_uint(b1)));
}
static __device__ __forceinline__ void cpa16(uint32_t d, const float* s) {
    asm volatile("cp.async.ca.shared.global [%0], [%1], 16;" :: "r"(d), "l"(s));
}
static __device__ __forceinline__ void cpa_commit() {
    asm volatile("cp.async.commit_group;");
}

constexpr size_t SMEM_QKV   = (size_t)NSTG * STGF * 4;   // 61440
constexpr size_t SMEM_FUSED =
    (size_t)(128 * QLD + 2 * KT * QLD + NP * CLD + 8 * 16 * CLD) * 4; // 189568

// =====================================================================
// Kernel 1: QKV, y = x @ W^T.  block 128x64, warps 4x2 (32x32 tiles),
// cp.async 4-stage pipeline, RNA cvt at frag load.  occ target 3 CTAs.
// grid (HD/64, 8192/128, 3)
// =====================================================================
__global__ void __launch_bounds__(256, 3)
qkv_gemm(const float* __restrict__ x, const float* __restrict__ Wq,
         const float* __restrict__ Wk, const float* __restrict__ Wv)
{
    extern __shared__ float sm[];
    const int mode = blockIdx.z;
    const float* Wm = (mode == 0) ? Wq : (mode == 1) ? Wk : Wv;
    float* dst      = (mode == 0) ? g_q : (mode == 1) ? g_k : g_v;
    const float scale = (mode == 0) ? 0.08838834764831845f : 1.0f;

    const int tid = threadIdx.x;
    const int m0 = blockIdx.y * 128, n0 = blockIdx.x * 64;
    const int arow = tid >> 1, acg = (tid & 1) * 4;
    const int brow = tid >> 2, bcg = (tid & 3) * 4;
    const float* ag = x  + (size_t)(m0 + arow) * HD_ + acg;
    const float* bg = Wm + (size_t)(n0 + brow) * HD_ + bcg;
    const uint32_t sbase = (uint32_t)__cvta_generic_to_shared(sm);
    const uint32_t aoff = (uint32_t)(arow * LQK + acg) * 4;
    const uint32_t boff = (uint32_t)(128 * LQK + brow * LQK + bcg) * 4;

    const int lane = tid & 31, wid = tid >> 5;
    const int wm = wid >> 1, wn = wid & 1, grp = lane >> 2, q4 = lane & 3;
    const int abase = (wm * 32 + grp) * LQK + q4;
    const int bbase = 128 * LQK + (wn * 32 + grp) * LQK + q4;

    float acc[2][4][4] = {};

    // prologue: 3 chunks in flight
#pragma unroll
    for (int c = 0; c < 3; ++c) {
        const uint32_t st = sbase + (uint32_t)(c & 3) * (STGF * 4);
        cpa16(st + aoff,      ag + c * 16);
        cpa16(st + aoff + 32, ag + c * 16 + 8);
        cpa16(st + boff,      bg + c * 16);
        cpa_commit();
    }

    constexpr int NCH = HD_ / 16;   // 64
    for (int kc = 0; kc < NCH; ++kc) {
        if (kc <= NCH - 3)      asm volatile("cp.async.wait_group 2;");
        else if (kc == NCH - 2) asm volatile("cp.async.wait_group 1;");
        else                    asm volatile("cp.async.wait_group 0;");
        __syncthreads();
        const float* Ss = sm + (kc & 3) * STGF;

#pragma unroll
        for (int k8 = 0; k8 < 16; k8 += 8) {
            float a[2][4], b[4][2];
#pragma unroll
            for (int i = 0; i < 2; ++i) {
                const int o = abase + i * 16 * LQK + k8;
                a[i][0] = tf32r(Ss[o]);     a[i][1] = tf32r(Ss[o + 8 * LQK]);
                a[i][2] = tf32r(Ss[o + 4]); a[i][3] = tf32r(Ss[o + 8 * LQK + 4]);
            }
#pragma unroll
            for (int j = 0; j < 4; ++j) {
                const int o = bbase + j * 8 * LQK + k8;
                b[j][0] = tf32r(Ss[o]); b[j][1] = tf32r(Ss[o + 4]);
            }
#pragma unroll
            for (int i = 0; i < 2; ++i)
#pragma unroll
                for (int j = 0; j < 4; ++j)
                    mma8(acc[i][j], a[i][0], a[i][1], a[i][2], a[i][3], b[j][0], b[j][1]);
        }
        __syncthreads();
        if (kc + 3 < NCH) {
            const int c = kc + 3;
            const uint32_t st = sbase + (uint32_t)(c & 3) * (STGF * 4);
            cpa16(st + aoff,      ag + c * 16);
            cpa16(st + aoff + 32, ag + c * 16 + 8);
            cpa16(st + boff,      bg + c * 16);
            cpa_commit();
        }
    }

#pragma unroll
    for (int i = 0; i < 2; ++i) {
#pragma unroll
        for (int r = 0; r < 2; ++r) {
            const int m = m0 + wm * 32 + i * 16 + grp + r * 8;
            const int bb = m >> 11, s = m & (S_ - 1);
#pragma unroll
            for (int j = 0; j < 4; ++j) {
                const int n = n0 + wn * 32 + j * 8 + 2 * q4;
                const int h = n >> 7, d = n & 127;
                float2 w = make_float2(acc[i][j][2 * r] * scale, acc[i][j][2 * r + 1] * scale);
                *(float2*)&dst[((size_t)(bb * NH_ + h) * S_ + s) * DK_ + d] = w;
            }
        }
    }
}

// =====================================================================
// Kernel 2: db4 DWT of v. cA -> out2 (raw), cD -> g_cDT (transposed).
// =====================================================================
__global__ void dwt_kernel(float* __restrict__ out2)
{
    const int rowi = blockIdx.x;
    const float* vr = g_v + (size_t)rowi * DK_;
    __shared__ float e[141];
    const int t = threadIdx.x;

    e[t + 6] = vr[t];
    if (t < 6)  e[t]       = vr[5 - t];
    if (t < 7)  e[134 + t] = vr[127 - t];
    __syncthreads();

    if (t < WA_) {
        float a = 0.f, d = 0.f;
#pragma unroll
        for (int u = 0; u < 8; ++u) {
            const float xv = e[2 * t + u];
            a += xv * REV_LO[u];
            d += xv * REV_HI[u];
        }
        out2[(size_t)rowi * WA_ + t] = a;
        const int bh = rowi >> 11, s = rowi & (S_ - 1);
        g_cDT[((size_t)bh * WA_ + t) * S_ + s] = d;
    }
}

// =====================================================================
// Kernel 3: FUSED attention (R4 version, measured best).  KT=64, occ 1.
// grid (16, 32), 256 threads, ~185KB smem.
// =====================================================================
__global__ void __launch_bounds__(256, 1)
fused_attn(float* __restrict__ out1)
{
    extern __shared__ float sm[];
    float* Qs  = sm;                              // 128 x QLD
    float* Kh  = Qs + 128 * QLD;                  // KT x QLD
    float* Kl  = Kh + KT * QLD;
    float* CDs = Kl + KT * QLD;                   // NP x CLD
    float* Ps  = CDs + NP * CLD;                  // 8 warps x 16 x CLD

    const int bh = blockIdx.y;
    const int q0 = blockIdx.x * 128;
    const int tid = threadIdx.x, lane = tid & 31, wid = tid >> 5;
    const int grp = lane >> 2, q4 = lane & 3;
    float* Pw = Ps + wid * (16 * CLD);

    {
        const int c = (tid & 31) * 4;
#pragma unroll
        for (int p = 0; p < 16; ++p) {
            const int r = (tid >> 5) + p * 8;
            *(float4*)&Qs[r * QLD + c] =
                *(const float4*)(g_q + ((size_t)bh * S_ + q0 + r) * DK_ + c);
        }
    }

    const int kcol = (tid & 31) * 4;
    const int ccol = (tid & 15) * 4;
    float4 kreg[8], creg[5];
#pragma unroll
    for (int p = 0; p < 8; ++p) {
        const int r = (tid >> 5) + p * 8;
        kreg[p] = *(const float4*)(g_k + ((size_t)bh * S_ + r) * DK_ + kcol);
    }
#pragma unroll
    for (int it = 0; it < 5; ++it) {
        const int n = (tid >> 4) + it * 16;
        creg[it] = (n < WA_) ? *(const float4*)(g_cDT + ((size_t)bh * WA_ + n) * S_ + ccol)
                             : make_float4(0.f, 0.f, 0.f, 0.f);
    }

    float oacc[9][4] = {};
    float m0v = -CUDART_INF_F, m1v = -CUDART_INF_F;
    float l0 = 0.f, l1 = 0.f;
    const int arow = wid * 16 + grp;

    for (int kc = 0; kc < S_ / KT; ++kc) {
        __syncthreads();
#pragma unroll
        for (int p = 0; p < 8; ++p) {
            const int r = (tid >> 5) + p * 8;
            float4 v = kreg[p];
            float4 h = tf32r4(v);
            float4 l = make_float4(tf32r(v.x - h.x), tf32r(v.y - h.y),
                                   tf32r(v.z - h.z), tf32r(v.w - h.w));
            *(float4*)&Kh[r * QLD + kcol] = h;
            *(float4*)&Kl[r * QLD + kcol] = l;
        }
#pragma unroll
        for (int it = 0; it < 5; ++it) {
            const int n = (tid >> 4) + it * 16;
            if (n < NP) *(float4*)&CDs[n * CLD + ccol] = tf32r4(creg[it]);
        }
        __syncthreads();
        if (kc + 1 < S_ / KT) {
            const size_t krow0 = (size_t)bh * S_ + (kc + 1) * KT;
#pragma unroll
            for (int p = 0; p < 8; ++p) {
                const int r = (tid >> 5) + p * 8;
                kreg[p] = *(const float4*)(g_k + (krow0 + r) * DK_ + kcol);
            }
#pragma unroll
            for (int it = 0; it < 5; ++it) {
                const int n = (tid >> 4) + it * 16;
                creg[it] = (n < WA_)
                    ? *(const float4*)(g_cDT + ((size_t)bh * WA_ + n) * S_ + (kc + 1) * KT + ccol)
                    : make_float4(0.f, 0.f, 0.f, 0.f);
            }
        }

        float sacc[8][4] = {};
#pragma unroll
        for (int k8 = 0; k8 < DK_; k8 += 8) {
            const int o = arow * QLD + q4 + k8;
            const float f0 = Qs[o], f1 = Qs[o + 8 * QLD];
            const float f2 = Qs[o + 4], f3 = Qs[o + 8 * QLD + 4];
            const float ah0 = tf32r(f0), ah1 = tf32r(f1), ah2 = tf32r(f2), ah3 = tf32r(f3);
            const float al0 = tf32r(f0 - ah0), al1 = tf32r(f1 - ah1);
            const float al2 = tf32r(f2 - ah2), al3 = tf32r(f3 - ah3);
#pragma unroll
            for (int j = 0; j < 8; ++j) {
                const int ob = (8 * j + grp) * QLD + q4 + k8;
                const float bh0 = Kh[ob], bh1 = Kh[ob + 4];
                const float bl0 = Kl[ob], bl1 = Kl[ob + 4];
                mma8(sacc[j], ah0, ah1, ah2, ah3, bh0, bh1);
                mma8(sacc[j], ah0, ah1, ah2, ah3, bl0, bl1);
                mma8(sacc[j], al0, al1, al2, al3, bh0, bh1);
            }
        }

        float tm0 = sacc[0][0], tm1 = sacc[0][2];
#pragma unroll
        for (int j = 0; j < 8; ++j) {
            tm0 = fmaxf(tm0, fmaxf(sacc[j][0], sacc[j][1]));
            tm1 = fmaxf(tm1, fmaxf(sacc[j][2], sacc[j][3]));
        }
        tm0 = fmaxf(tm0, __shfl_xor_sync(0xFFFFFFFFu, tm0, 1));
        tm0 = fmaxf(tm0, __shfl_xor_sync(0xFFFFFFFFu, tm0, 2));
        tm1 = fmaxf(tm1, __shfl_xor_sync(0xFFFFFFFFu, tm1, 1));
        tm1 = fmaxf(tm1, __shfl_xor_sync(0xFFFFFFFFu, tm1, 2));
        const float mn0 = fmaxf(m0v, tm0), mn1 = fmaxf(m1v, tm1);
        const float a0s = __expf(m0v - mn0), a1s = __expf(m1v - mn1);

        float ts0 = 0.f, ts1 = 0.f;
#pragma unroll
        for (int j = 0; j < 8; ++j) {
            const float p0 = __expf(sacc[j][0] - mn0);
            const float p1 = __expf(sacc[j][1] - mn0);
            const float p2 = __expf(sacc[j][2] - mn1);
            const float p3 = __expf(sacc[j][3] - mn1);
            ts0 += p0 + p1; ts1 += p2 + p3;
            *(float2*)&Pw[grp * CLD + 8 * j + 2 * q4] = make_float2(tf32r(p0), tf32r(p1));
            *(float2*)&Pw[(grp + 8) * CLD + 8 * j + 2 * q4] = make_float2(tf32r(p2), tf32r(p3));
        }
        ts0 += __shfl_xor_sync(0xFFFFFFFFu, ts0, 1);
        ts0 += __shfl_xor_sync(0xFFFFFFFFu, ts0, 2);
        ts1 += __shfl_xor_sync(0xFFFFFFFFu, ts1, 1);
        ts1 += __shfl_xor_sync(0xFFFFFFFFu, ts1, 2);
        l0 = l0 * a0s + ts0;
        l1 = l1 * a1s + ts1;
        m0v = mn0; m1v = mn1;
#pragma unroll
        for (int n = 0; n < 9; ++n) {
            oacc[n][0] *= a0s; oacc[n][1] *= a0s;
            oacc[n][2] *= a1s; oacc[n][3] *= a1s;
        }
        __syncwarp();

#pragma unroll
        for (int k8 = 0; k8 < KT; k8 += 8) {
            const int o = grp * CLD + q4 + k8;
            const float a0 = Pw[o], a1 = Pw[o + 8 * CLD];
            const float a2 = Pw[o + 4], a3 = Pw[o + 8 * CLD + 4];
#pragma unroll
            for (int n = 0; n < 9; ++n) {
                const int ob = (8 * n + grp) * CLD + q4 + k8;
                mma8(oacc[n], a0, a1, a2, a3, CDs[ob], CDs[ob + 4]);
            }
        }
        __syncwarp();
    }

    const int bb = bh >> 3, hh = bh & 7;
    const float i0 = 1.0f / l0, i1 = 1.0f / l1;
    const int s0 = q0 + wid * 16 + grp, s1 = s0 + 8;
    float* o0 = out1 + (size_t)(bb * S_ + s0) * OUT1W_ + hh * WA_;
    float* o1 = out1 + (size_t)(bb * S_ + s1) * OUT1W_ + hh * WA_;
#pragma unroll
    for (int n = 0; n < 9; ++n) {
        const int c = 8 * n + 2 * q4;
        if (c < WA_)     { o0[c]     = oacc[n][0] * i0; o1[c]     = oacc[n][2] * i1; }
        if (c + 1 < WA_) { o0[c + 1] = oacc[n][1] * i0; o1[c + 1] = oacc[n][3] * i1; }
    }
}

// =====================================================================
extern "C" void kernel_launch(void* const* d_in, const int* in_sizes, int n_in,
                              void* d_out, int out_size)
{
    const float* x  = (const float*)d_in[0];
    const float* Wq = (const float*)d_in[1];
    const float* Wk = (const float*)d_in[2];
    const float* Wv = (const float*)d_in[3];

    float* out1 = (float*)d_out;
    float* out2 = out1 + (size_t)out_size / 2;

    cudaFuncSetAttribute(qkv_gemm,   cudaFuncAttributeMaxDynamicSharedMemorySize, (int)SMEM_QKV);
    cudaFuncSetAttribute(fused_attn, cudaFuncAttributeMaxDynamicSharedMemorySize, (int)SMEM_FUSED);

    qkv_gemm  <<<dim3(HD_ / 64, (B_ * S_) / 128, 3), 256, SMEM_QKV>>>(x, Wq, Wk, Wv);
    dwt_kernel<<<BH_ * S_, 128>>>(out2);
    fused_attn<<<dim3(S_ / 128, BH_), 256, SMEM_FUSED>>>(out1);
}